// round 11
// baseline (speedup 1.0000x reference)
#include <cuda_runtime.h>

#define T_DIM 512
#define B_DIM 256
#define N_DIM 128
#define BN    (B_DIM * N_DIM)
#define NCHUNK 128
#define TCHUNK (T_DIM / NCHUNK)
#define NFCTA  148
#define SLOTS  2
#define PSTR   68                    /* 64 floats + 16B pad per K-half */

#define LOGC_F 5.545177444479562f    /* ln 256 */
#define LOGC_D 5.545177444479562

__device__ float g_score[B_DIM];
__device__ float g_logZ[B_DIM];
__device__ int   g_len[B_DIM];
__device__ float g_part_s[NCHUNK * B_DIM];
__device__ int   g_part_c[NCHUNK * B_DIM];
__device__ int   g_units[B_DIM];          /* b sorted by len desc */
__device__ float g_vec[2][B_DIM][N_DIM];  /* meeting vectors */
__device__ float g_acc[2][B_DIM];         /* accumulated log scales */
__device__ int   g_ctr[2];                /* unit pop counters (self-reset) */
__device__ int   g_pairdone[B_DIM];       /* per-b arrival (self-reset) */
__device__ unsigned int g_done;           /* CTA completion (self-reset) */

// ---------------- f32x2 helpers ----------------
__device__ __forceinline__ unsigned long long pack2(float lo, float hi) {
    unsigned long long u;
    asm("mov.b64 %0, {%1,%2};" : "=l"(u) : "f"(lo), "f"(hi));
    return u;
}
__device__ __forceinline__ void unpack2(unsigned long long u, float& lo, float& hi) {
    asm("mov.b64 {%0,%1}, %2;" : "=f"(lo), "=f"(hi) : "l"(u));
}
__device__ __forceinline__ void ffma2(unsigned long long& d,
                                      unsigned long long a, unsigned long long b) {
    asm("fma.rn.f32x2 %0, %1, %2, %0;" : "+l"(d) : "l"(a), "l"(b));
}

// ---------------------------------------------------------------------------
// A1: coalesced partial gold-path score + count per t-chunk. thread = b.
// ---------------------------------------------------------------------------
__global__ void scoreA1(const float* __restrict__ emit,
                        const int*   __restrict__ target,
                        const int*   __restrict__ mask,
                        const float* __restrict__ trans) {
    const int b = threadIdx.x;
    const int c = blockIdx.x;
    const int t0 = c * TCHUNK;
    float s = 0.f; int cnt = 0;
    #pragma unroll
    for (int t = t0; t < t0 + TCHUNK; ++t) {
        if (mask[t * B_DIM + b] != 0) {
            int tg = target[t * B_DIM + b];
            float v = emit[(size_t)t * BN + b * N_DIM + tg];
            if (t > 0) {
                int tp = target[(t - 1) * B_DIM + b];
                v += trans[tp * N_DIM + tg];
            }
            s += v; cnt += 1;
        }
    }
    g_part_s[c * B_DIM + b] = s;
    g_part_c[c * B_DIM + b] = cnt;
}

// ---------------------------------------------------------------------------
// A2: combine partials + bonuses; bitonic sort b by length DESC -> unit list.
// ---------------------------------------------------------------------------
__global__ void scoreA2(const int*   __restrict__ target,
                        const float* __restrict__ strans,
                        const float* __restrict__ etrans) {
    __shared__ int key[B_DIM];
    const int b = threadIdx.x;
    float s = 0.f; int cnt = 0;
    for (int c = 0; c < NCHUNK; ++c) {
        s   += g_part_s[c * B_DIM + b];
        cnt += g_part_c[c * B_DIM + b];
    }
    s += strans[target[b]];
    s += etrans[target[(cnt - 1) * B_DIM + b]];
    g_score[b] = s;
    g_len[b]   = cnt;
    key[b] = (cnt << 9) | b;
    __syncthreads();

    for (int k = 2; k <= B_DIM; k <<= 1) {
        for (int jj = k >> 1; jj > 0; jj >>= 1) {
            int p = b ^ jj;
            if (p > b) {
                int a0 = key[b], a1 = key[p];
                bool desc = ((b & k) != 0);
                if ((a0 > a1) == desc) { key[b] = a1; key[p] = a0; }
            }
            __syncthreads();
        }
    }
    g_units[b] = key[b] & 511;
}

// ---------------------------------------------------------------------------
// Forward kernel: 148 CTAs x 256 threads = 2 chain slots x 128 threads.
// Each slot runs TWO batch units (adjacent in sorted order -> near-equal
// lengths) in lockstep: per step 32 LDS.128 + 128 FFMA2 + ONE barrier for
// two matvecs. Thread (jp, h): h = K-half, owns j0=2jp, j1. E (2 columns x
// K-half) in 128 regs, shared by both units. Joint phase = min steps, then
// the longer unit finishes solo. Renorm every 32 steps. Work stealing pops
// 2 units at a time. Second finisher per b computes the meeting dot;
// last CTA does the fused (logZ-score)/B reduction + state reset.
// ---------------------------------------------------------------------------
__global__ void __launch_bounds__(256, 1)
forward_kernel(const float* __restrict__ emit,
               const float* __restrict__ trans,
               const float* __restrict__ strans,
               const float* __restrict__ etrans,
               float* __restrict__ out) {
    __shared__ __align__(16) float pbuf[SLOTS][2][2][2 * PSTR]; // slot, unit, pingpong
    __shared__ float  wsum[SLOTS][2][4];
    __shared__ int    s_idx[SLOTS];
    __shared__ int    s_old[SLOTS][2];
    __shared__ int    sflag;
    __shared__ double shd[B_DIM];

    const int tid    = threadIdx.x;
    const int lane   = tid & 31;
    const int slot   = tid >> 7;              // 0..1
    const int stid   = tid & 127;
    const int h      = stid & 1;              // K-half
    const int jp     = stid >> 1;             // 0..63
    const int j0     = 2 * jp, j1 = j0 + 1;
    const int swarp  = stid >> 5;             // 0..3 within slot
    const int sg     = blockIdx.x * SLOTS + slot;
    const int orient = sg & 1;                // 0 = fwd, 1 = bwd
    const int widx   = j0 + ((j0 >> 6) << 2); // padded store index for p[j0]

    #define BARS() asm volatile("bar.sync %0, 128;" :: "r"(slot + 1) : "memory")

    // E half-columns (fwd) / half-rows (bwd) for j0, j1; i-pair packed.
    unsigned long long E2A[32], E2B[32];
    if (orient == 0) {
        #pragma unroll
        for (int m = 0; m < 32; ++m) {
            int i = 64 * h + 2 * m;
            E2A[m] = pack2(__expf(trans[i * N_DIM + j0]),
                           __expf(trans[(i + 1) * N_DIM + j0]));
            E2B[m] = pack2(__expf(trans[i * N_DIM + j1]),
                           __expf(trans[(i + 1) * N_DIM + j1]));
        }
    } else {
        #pragma unroll
        for (int m = 0; m < 32; ++m) {
            int i = 64 * h + 2 * m;
            E2A[m] = pack2(__expf(trans[j0 * N_DIM + i]),
                           __expf(trans[j0 * N_DIM + i + 1]));
            E2B[m] = pack2(__expf(trans[j1 * N_DIM + i]),
                           __expf(trans[j1 * N_DIM + i + 1]));
        }
    }
    const float sj0  = strans[j0], sj1 = strans[j1];
    const float etj0 = etrans[j0], etj1 = etrans[j1];
    const int roff = 17 * h;                  // ulonglong2 offset of my K-half

    // one matvec for unit U (p read pointer PR, result (V0,V1), scales)
    #define MV(PR, EE0, EE1, V0, V1) do {                                    \
        const ulonglong2* pu = (const ulonglong2*)(PR) + roff;               \
        unsigned long long a0 = 0ull, a1 = 0ull, b0 = 0ull, b1 = 0ull;       \
        _Pragma("unroll")                                                    \
        for (int k = 0; k < 16; ++k) {                                       \
            ulonglong2 x = pu[k];                                            \
            ffma2(a0, x.x, E2A[2 * k]);                                      \
            ffma2(a1, x.y, E2A[2 * k + 1]);                                  \
            ffma2(b0, x.x, E2B[2 * k]);                                      \
            ffma2(b1, x.y, E2B[2 * k + 1]);                                  \
        }                                                                    \
        float f0, f1, f2, f3, g0, g1, g2, g3;                                \
        unpack2(a0, f0, f1); unpack2(a1, f2, f3);                            \
        unpack2(b0, g0, g1); unpack2(b1, g2, g3);                            \
        float s0 = (f0 + f1) + (f2 + f3);                                    \
        float s1 = (g0 + g1) + (g2 + g3);                                    \
        s0 += __shfl_xor_sync(0xffffffffu, s0, 1);                           \
        s1 += __shfl_xor_sync(0xffffffffu, s1, 1);                           \
        V0 = s0 * (EE0); V1 = s1 * (EE1);                                    \
    } while (0)

    #define RED4(R, WS) do {                                                 \
        _Pragma("unroll")                                                    \
        for (int o = 16; o; o >>= 1)                                         \
            R += __shfl_xor_sync(0xffffffffu, R, o);                         \
        if (lane == 0) (WS)[swarp] = R;                                      \
    } while (0)

    #define PUBLISH(B, LEN, V0, V1, ACC) do {                                \
        if (h == 0) {                                                        \
            g_vec[orient][B][j0] = V0;                                       \
            g_vec[orient][B][j1] = V1;                                       \
            if (stid == 0) g_acc[orient][B] = ACC;                           \
        }                                                                    \
        __threadfence();                                                     \
        BARS();                                                              \
        if (stid == 0) s_old[slot][0] = atomicAdd(&g_pairdone[B], 1);        \
        BARS();                                                              \
        if (s_old[slot][0] == 1) {                                           \
            __threadfence();                                                 \
            float r = h ? 0.f : ((V0) * g_vec[orient ^ 1][B][j0]             \
                               + (V1) * g_vec[orient ^ 1][B][j1]);           \
            RED4(r, wsum[slot][0]);                                          \
            BARS();                                                          \
            if (stid == 0) {                                                 \
                float dot = (wsum[slot][0][0] + wsum[slot][0][1])            \
                          + (wsum[slot][0][2] + wsum[slot][0][3]);           \
                g_logZ[B] = (float)((double)(ACC)                            \
                                    + (double)g_acc[orient ^ 1][B]           \
                                    + (double)(LEN - 1) * LOGC_D             \
                                    + log((double)dot));                     \
            }                                                                \
            BARS();                                                          \
        }                                                                    \
    } while (0)

    // ---- work-stealing: pop 2 units at a time ----
    for (;;) {
        if (stid == 0) s_idx[slot] = atomicAdd(&g_ctr[orient], 2);
        BARS();
        const int idx = s_idx[slot];
        if (idx >= B_DIM) break;

        const int  bA   = g_units[idx];
        const bool hasB = (idx + 1 < B_DIM);
        const int  bB   = hasB ? g_units[idx + 1] : bA;

        const int lenA = g_len[bA];
        const int mA   = (lenA - 1) >> 1;
        const int nA   = orient ? (lenA - 1 - mA) : mA;
        const int lastA = orient ? nA : -1;
        const int lenB = g_len[bB];
        const int mB   = (lenB - 1) >> 1;
        const int nB   = hasB ? (orient ? (lenB - 1 - mB) : mB) : 0;
        const int lastB = orient ? nB : -1;

        const int e0iA = orient ? (lenA - 1) : 0;
        const int e0iB = orient ? (lenB - 1) : 0;
        const int es   = orient ? -1 : 1;
        const float* ebA = emit + bA * N_DIM + j0;
        const float* ebB = emit + bB * N_DIM + j0;

        #define LDEA(TT) (*(const float2*)(ebA + (size_t)max(0, min(lenA - 1, e0iA + es * (TT))) * BN))
        #define LDEB(TT) (*(const float2*)(ebB + (size_t)max(0, min(lenB - 1, e0iB + es * (TT))) * BN))

        float accA = 0.f, accB = 0.f;
        float vA0, vA1, vB0, vB1;

        // ---- init unit A ----
        if (orient == 0) {
            float2 e0v = *(const float2*)ebA;
            vA0 = __expf(sj0 + e0v.x); vA1 = __expf(sj1 + e0v.y);
        } else if (nA == 0) {
            vA0 = __expf(etj0); vA1 = __expf(etj1);
        } else {
            float2 e0v = *(const float2*)(ebA + (size_t)(lenA - 1) * BN);
            vA0 = __expf(e0v.x + etj0 - LOGC_F);
            vA1 = __expf(e0v.y + etj1 - LOGC_F);
        }
        // ---- init unit B ----
        if (!hasB) { vB0 = vB1 = 0.f; }
        else if (orient == 0) {
            float2 e0v = *(const float2*)ebB;
            vB0 = __expf(sj0 + e0v.x); vB1 = __expf(sj1 + e0v.y);
        } else if (nB == 0) {
            vB0 = __expf(etj0); vB1 = __expf(etj1);
        } else {
            float2 e0v = *(const float2*)(ebB + (size_t)(lenB - 1) * BN);
            vB0 = __expf(e0v.x + etj0 - LOGC_F);
            vB1 = __expf(e0v.y + etj1 - LOGC_F);
        }

        float* prA = pbuf[slot][0][0]; float* pwA = pbuf[slot][0][1];
        float* prB = pbuf[slot][1][0]; float* pwB = pbuf[slot][1][1];
        if (h == 0) {
            *(float2*)&prA[widx] = make_float2(vA0, vA1);
            *(float2*)&prB[widx] = make_float2(vB0, vB1);
        }

        int t = 1;
        const int nmin = hasB ? min(nA, nB) : 0;   // sorted desc: usually nB

        // ================= joint phase: t = 1..nmin =================
        if (nmin > 0) {
            float2 eA0 = LDEA(1), eA1 = LDEA(2);
            float2 eB0 = LDEB(1), eB1 = LDEB(2);
            BARS();
            #pragma unroll 1
            for (; t <= nmin; ++t) {
                float eeA0 = (t == lastA) ? 1.f : __expf(eA0.x - LOGC_F);
                float eeA1 = (t == lastA) ? 1.f : __expf(eA0.y - LOGC_F);
                float eeB0 = (t == lastB) ? 1.f : __expf(eB0.x - LOGC_F);
                float eeB1 = (t == lastB) ? 1.f : __expf(eB0.y - LOGC_F);
                eA0 = eA1; eA1 = LDEA(t + 2);
                eB0 = eB1; eB1 = LDEB(t + 2);

                MV(prA, eeA0, eeA1, vA0, vA1);
                MV(prB, eeB0, eeB1, vB0, vB1);

                if ((t & 31) == 0) {
                    float rA = h ? 0.f : (vA0 + vA1);
                    float rB = h ? 0.f : (vB0 + vB1);
                    RED4(rA, wsum[slot][0]);
                    RED4(rB, wsum[slot][1]);
                    BARS();
                    float ssA = (wsum[slot][0][0] + wsum[slot][0][1])
                              + (wsum[slot][0][2] + wsum[slot][0][3]);
                    float ssB = (wsum[slot][1][0] + wsum[slot][1][1])
                              + (wsum[slot][1][2] + wsum[slot][1][3]);
                    vA0 *= (1.f / ssA); vA1 *= (1.f / ssA);
                    vB0 *= (1.f / ssB); vB1 *= (1.f / ssB);
                    accA += __logf(ssA); accB += __logf(ssB);
                }
                if (h == 0) {
                    *(float2*)&pwA[widx] = make_float2(vA0, vA1);
                    *(float2*)&pwB[widx] = make_float2(vB0, vB1);
                }
                { float* tmp = prA; prA = pwA; pwA = tmp; }
                { float* tmp = prB; prB = pwB; pwB = tmp; }
                BARS();
            }
        }

        // publish the (usually) shorter unit B
        if (hasB && nB == nmin) PUBLISH(bB, lenB, vB0, vB1, accB);

        // ================= solo phase for A: t = nmin+1..nA =================
        if (nA > nmin) {
            float2 eA0 = LDEA(t), eA1 = LDEA(t + 1);
            BARS();
            #pragma unroll 1
            for (; t <= nA; ++t) {
                float eeA0 = (t == lastA) ? 1.f : __expf(eA0.x - LOGC_F);
                float eeA1 = (t == lastA) ? 1.f : __expf(eA0.y - LOGC_F);
                eA0 = eA1; eA1 = LDEA(t + 2);

                MV(prA, eeA0, eeA1, vA0, vA1);

                if ((t & 31) == 0) {
                    float rA = h ? 0.f : (vA0 + vA1);
                    RED4(rA, wsum[slot][0]);
                    BARS();
                    float ssA = (wsum[slot][0][0] + wsum[slot][0][1])
                              + (wsum[slot][0][2] + wsum[slot][0][3]);
                    vA0 *= (1.f / ssA); vA1 *= (1.f / ssA);
                    accA += __logf(ssA);
                }
                if (h == 0) *(float2*)&pwA[widx] = make_float2(vA0, vA1);
                { float* tmp = prA; prA = pwA; pwA = tmp; }
                BARS();
            }
        }

        PUBLISH(bA, lenA, vA0, vA1, accA);
        #undef LDEA
        #undef LDEB
    }
    #undef MV
    #undef RED4
    #undef PUBLISH
    #undef BARS

    // ---- fused final reduction + state reset (last CTA) ----
    __syncthreads();
    if (tid == 0) {
        __threadfence();
        unsigned int old = atomicAdd(&g_done, 1u);
        sflag = (old == NFCTA - 1) ? 1 : 0;
    }
    __syncthreads();
    if (sflag) {
        __threadfence();
        if (tid < 128) {
            shd[tid]       = (double)g_logZ[tid]       - (double)g_score[tid];
            shd[tid + 128] = (double)g_logZ[tid + 128] - (double)g_score[tid + 128];
            g_pairdone[tid]       = 0;
            g_pairdone[tid + 128] = 0;
        }
        if (tid < 2) g_ctr[tid] = 0;
        __syncthreads();
        for (int o = 128; o; o >>= 1) {
            if (tid < o) shd[tid] += shd[tid + o];
            __syncthreads();
        }
        if (tid == 0) {
            out[0] = (float)(shd[0] / (double)B_DIM);
            g_done = 0;
        }
    }
}

extern "C" void kernel_launch(void* const* d_in, const int* in_sizes, int n_in,
                              void* d_out, int out_size) {
    const float* emit   = (const float*)d_in[0];
    const int*   target = (const int*)d_in[1];
    const int*   mask   = (const int*)d_in[2];
    const float* trans  = (const float*)d_in[3];
    const float* strans = (const float*)d_in[4];
    const float* etrans = (const float*)d_in[5];

    scoreA1<<<NCHUNK, B_DIM>>>(emit, target, mask, trans);
    scoreA2<<<1, B_DIM>>>(target, strans, etrans);
    forward_kernel<<<NFCTA, 256>>>(emit, trans, strans, etrans, (float*)d_out);
}

// round 12
// speedup vs baseline: 1.0847x; 1.0847x over previous
#include <cuda_runtime.h>

#define T_DIM 512
#define B_DIM 256
#define N_DIM 128
#define BN    (B_DIM * N_DIM)
#define NCHUNK 256
#define TCHUNK (T_DIM / NCHUNK)
#define NFCTA  148
#define SLOTS  3
#define PSTR   68                    /* 64 floats + 16B pad per K-half */

#define LOGC_F 5.545177444479562f    /* ln 256 */
#define LOGC_D 5.545177444479562

__device__ float g_score[B_DIM];
__device__ float g_logZ[B_DIM];
__device__ int   g_len[B_DIM];
__device__ float g_part_s[NCHUNK * B_DIM];
__device__ int   g_part_c[NCHUNK * B_DIM];
__device__ int   g_units[B_DIM];          /* b sorted by len desc */
__device__ float g_vec[2][B_DIM][N_DIM];  /* meeting vectors */
__device__ float g_acc[2][B_DIM];         /* accumulated log scales */
__device__ int   g_ctr[2];                /* unit pop counters (self-reset) */
__device__ int   g_pairdone[B_DIM];       /* per-b arrival (self-reset) */
__device__ unsigned int g_done;           /* CTA completion (self-reset) */

// ---------------- f32x2 helpers ----------------
__device__ __forceinline__ unsigned long long pack2(float lo, float hi) {
    unsigned long long u;
    asm("mov.b64 %0, {%1,%2};" : "=l"(u) : "f"(lo), "f"(hi));
    return u;
}
__device__ __forceinline__ void unpack2(unsigned long long u, float& lo, float& hi) {
    asm("mov.b64 {%0,%1}, %2;" : "=f"(lo), "=f"(hi) : "l"(u));
}
__device__ __forceinline__ void ffma2(unsigned long long& d,
                                      unsigned long long a, unsigned long long b) {
    asm("fma.rn.f32x2 %0, %1, %2, %0;" : "+l"(d) : "l"(a), "l"(b));
}

// ---------------------------------------------------------------------------
// A1: coalesced partial gold-path score + count per t-chunk. thread = b.
// ---------------------------------------------------------------------------
__global__ void scoreA1(const float* __restrict__ emit,
                        const int*   __restrict__ target,
                        const int*   __restrict__ mask,
                        const float* __restrict__ trans) {
    const int b = threadIdx.x;
    const int c = blockIdx.x;
    const int t0 = c * TCHUNK;
    float s = 0.f; int cnt = 0;
    #pragma unroll
    for (int t = t0; t < t0 + TCHUNK; ++t) {
        if (mask[t * B_DIM + b] != 0) {
            int tg = target[t * B_DIM + b];
            float v = emit[(size_t)t * BN + b * N_DIM + tg];
            if (t > 0) {
                int tp = target[(t - 1) * B_DIM + b];
                v += trans[tp * N_DIM + tg];
            }
            s += v; cnt += 1;
        }
    }
    g_part_s[c * B_DIM + b] = s;
    g_part_c[c * B_DIM + b] = cnt;
}

// ---------------------------------------------------------------------------
// A2: combine partials + bonuses; bitonic sort b by length DESC -> unit list.
// ---------------------------------------------------------------------------
__global__ void scoreA2(const int*   __restrict__ target,
                        const float* __restrict__ strans,
                        const float* __restrict__ etrans) {
    __shared__ int key[B_DIM];
    const int b = threadIdx.x;
    float s = 0.f; int cnt = 0;
    for (int c = 0; c < NCHUNK; ++c) {
        s   += g_part_s[c * B_DIM + b];
        cnt += g_part_c[c * B_DIM + b];
    }
    s += strans[target[b]];
    s += etrans[target[(cnt - 1) * B_DIM + b]];
    g_score[b] = s;
    g_len[b]   = cnt;
    key[b] = (cnt << 9) | b;
    __syncthreads();

    for (int k = 2; k <= B_DIM; k <<= 1) {
        for (int jj = k >> 1; jj > 0; jj >>= 1) {
            int p = b ^ jj;
            if (p > b) {
                int a0 = key[b], a1 = key[p];
                bool desc = ((b & k) != 0);
                if ((a0 > a1) == desc) { key[b] = a1; key[p] = a0; }
            }
            __syncthreads();
        }
    }
    g_units[b] = key[b] & 511;
}

// ---------------------------------------------------------------------------
// Forward kernel: 148 CTAs x 384 threads = 3 chain slots x 128 threads
// (3 warps/SMSP, independent chains fill dependency gaps).
// Slot thread (jp, h): h = stid&1 K-half, jp = stid>>1 -> owns j0=2jp, j1.
// Per step per thread: 16 LDS.128 + 64 FFMA2 + 2 shfl + 1 bar.
// E (2 columns x K-half) = 128 regs; overhead trimmed to fit 168-reg cap.
// Static x4-unrolled ping-pong + 4-deep emit ring (no local memory).
// Work-stealing over 512 half-units sorted desc (LPT). Renorm every 32
// steps. Second finisher per b computes the meeting dot; last CTA does the
// fused (logZ-score)/B reduction + state reset.
// ---------------------------------------------------------------------------
__global__ void __launch_bounds__(384, 1)
forward_kernel(const float* __restrict__ emit,
               const float* __restrict__ trans,
               const float* __restrict__ strans,
               const float* __restrict__ etrans,
               float* __restrict__ out) {
    __shared__ __align__(16) float pbuf[SLOTS][2][2 * PSTR];
    __shared__ float  wsum[SLOTS][4];
    __shared__ int    s_idx[SLOTS];
    __shared__ int    s_old[SLOTS];
    __shared__ int    sflag;
    __shared__ double shd[B_DIM];

    const int tid    = threadIdx.x;
    const int lane   = tid & 31;
    const int slot   = tid >> 7;              // 0..2
    const int stid   = tid & 127;
    const int h      = stid & 1;              // K-half
    const int jp     = stid >> 1;             // 0..63
    const int j0     = 2 * jp, j1 = j0 + 1;
    const int swarp  = stid >> 5;             // 0..3 within slot
    const int sg     = blockIdx.x * SLOTS + slot;
    const int orient = sg & 1;                // 0 = fwd, 1 = bwd
    const int widx   = j0 + ((j0 >> 6) << 2); // padded store index for p[j0]

    #define BARS() asm volatile("bar.sync %0, 128;" :: "r"(slot + 1) : "memory")

    // E half-columns (fwd) / half-rows (bwd) for j0 and j1, i-pair packed.
    unsigned long long E2A[32], E2B[32];
    if (orient == 0) {
        #pragma unroll
        for (int m = 0; m < 32; ++m) {
            int i = 64 * h + 2 * m;
            E2A[m] = pack2(__expf(trans[i * N_DIM + j0]),
                           __expf(trans[(i + 1) * N_DIM + j0]));
            E2B[m] = pack2(__expf(trans[i * N_DIM + j1]),
                           __expf(trans[(i + 1) * N_DIM + j1]));
        }
    } else {
        #pragma unroll
        for (int m = 0; m < 32; ++m) {
            int i = 64 * h + 2 * m;
            E2A[m] = pack2(__expf(trans[j0 * N_DIM + i]),
                           __expf(trans[j0 * N_DIM + i + 1]));
            E2B[m] = pack2(__expf(trans[j1 * N_DIM + i]),
                           __expf(trans[j1 * N_DIM + i + 1]));
        }
    }

    float* pb0 = pbuf[slot][0];
    float* pb1 = pbuf[slot][1];
    const int roff = 17 * h;                  // ulonglong2 offset of my K-half

    float v0, v1;

    #define STEP(ECRAW, PR, PW, TT) do {                                     \
        float ee = ((TT) == lastSpec) ? 0.f : ((ECRAW).x - LOGC_F);          \
        float ef = ((TT) == lastSpec) ? 0.f : ((ECRAW).y - LOGC_F);          \
        float ee0 = __expf(ee), ee1 = __expf(ef);                            \
        const ulonglong2* pu = (const ulonglong2*)(PR) + roff;               \
        unsigned long long a0 = 0ull, a1 = 0ull, b0 = 0ull, b1 = 0ull;       \
        _Pragma("unroll")                                                    \
        for (int k = 0; k < 16; ++k) {                                       \
            ulonglong2 x = pu[k];                                            \
            ffma2(a0, x.x, E2A[2 * k]);                                      \
            ffma2(a1, x.y, E2A[2 * k + 1]);                                  \
            ffma2(b0, x.x, E2B[2 * k]);                                      \
            ffma2(b1, x.y, E2B[2 * k + 1]);                                  \
        }                                                                    \
        float f0, f1, f2, f3, g0, g1, g2, g3;                                \
        unpack2(a0, f0, f1); unpack2(a1, f2, f3);                            \
        unpack2(b0, g0, g1); unpack2(b1, g2, g3);                            \
        float s0 = (f0 + f1) + (f2 + f3);                                    \
        float s1 = (g0 + g1) + (g2 + g3);                                    \
        s0 += __shfl_xor_sync(0xffffffffu, s0, 1);                           \
        s1 += __shfl_xor_sync(0xffffffffu, s1, 1);                           \
        v0 = s0 * ee0; v1 = s1 * ee1;                                        \
        if (((TT) & 31) == 0) {                                              \
            float r = h ? 0.f : (v0 + v1);                                   \
            _Pragma("unroll")                                                \
            for (int o = 16; o; o >>= 1)                                     \
                r += __shfl_xor_sync(0xffffffffu, r, o);                     \
            if (lane == 0) wsum[slot][swarp] = r;                            \
            BARS();                                                          \
            float ss = (wsum[slot][0] + wsum[slot][1])                       \
                     + (wsum[slot][2] + wsum[slot][3]);                      \
            float inv = 1.f / ss;                                            \
            v0 *= inv; v1 *= inv;                                            \
            acc_log += __logf(ss);                                           \
        }                                                                    \
        if (h == 0) *(float2*)&(PW)[widx] = make_float2(v0, v1);             \
        BARS();                                                              \
    } while (0)

    // ---- work-stealing unit loop ----
    for (;;) {
        if (stid == 0) s_idx[slot] = atomicAdd(&g_ctr[orient], 1);
        BARS();
        const int idx = s_idx[slot];
        if (idx >= B_DIM) break;

        const int b   = g_units[idx];
        const int len = g_len[b];
        const int m   = (len - 1) >> 1;
        const int nsteps   = orient ? (len - 1 - m) : m;
        const int lastSpec = orient ? nsteps : -1;
        const int e0i      = orient ? (len - 1) : 0;
        const int estep    = orient ? -1 : 1;
        const float* eb    = emit + b * N_DIM + j0;

        float acc_log = 0.f;
        if (orient == 0) {
            float2 e0v = *(const float2*)eb;
            v0 = __expf(strans[j0] + e0v.x);
            v1 = __expf(strans[j1] + e0v.y);
        } else if (nsteps == 0) {
            v0 = __expf(etrans[j0]);
            v1 = __expf(etrans[j1]);
        } else {
            float2 e0v = *(const float2*)(eb + (size_t)(len - 1) * BN);
            v0 = __expf(e0v.x + etrans[j0] - LOGC_F);
            v1 = __expf(e0v.y + etrans[j1] - LOGC_F);
        }

        if (nsteps > 0) {
            if (h == 0) *(float2*)&pb0[widx] = make_float2(v0, v1);
            #define LDE(TT) (*(const float2*)(eb + (size_t)max(0, min(len - 1, e0i + estep * (TT))) * BN))
            float2 e0 = LDE(1), e1 = LDE(2), e2 = LDE(3), e3 = LDE(4);
            BARS();
            int t = 1;
            #pragma unroll 1
            for (; t + 3 <= nsteps; t += 4) {
                float2 n0 = LDE(t + 4), n1 = LDE(t + 5),
                       n2 = LDE(t + 6), n3 = LDE(t + 7);
                STEP(e0, pb0, pb1, t);
                STEP(e1, pb1, pb0, t + 1);
                STEP(e2, pb0, pb1, t + 2);
                STEP(e3, pb1, pb0, t + 3);
                e0 = n0; e1 = n1; e2 = n2; e3 = n3;
            }
            if (t <= nsteps) { STEP(e0, pb0, pb1, t); ++t; }
            if (t <= nsteps) { STEP(e1, pb1, pb0, t); ++t; }
            if (t <= nsteps) { STEP(e2, pb0, pb1, t); }
            #undef LDE
        }

        // publish this half; second finisher computes the meeting dot.
        if (h == 0) {
            g_vec[orient][b][j0] = v0;
            g_vec[orient][b][j1] = v1;
            if (stid == 0) g_acc[orient][b] = acc_log;
        }
        __threadfence();
        BARS();
        if (stid == 0) s_old[slot] = atomicAdd(&g_pairdone[b], 1);
        BARS();
        if (s_old[slot] == 1) {
            __threadfence();
            float r = h ? 0.f : (v0 * g_vec[orient ^ 1][b][j0]
                               + v1 * g_vec[orient ^ 1][b][j1]);
            #pragma unroll
            for (int o = 16; o; o >>= 1)
                r += __shfl_xor_sync(0xffffffffu, r, o);
            if (lane == 0) wsum[slot][swarp] = r;
            BARS();
            if (stid == 0) {
                float dot = (wsum[slot][0] + wsum[slot][1])
                          + (wsum[slot][2] + wsum[slot][3]);
                g_logZ[b] = (float)((double)acc_log
                                    + (double)g_acc[orient ^ 1][b]
                                    + (double)(len - 1) * LOGC_D
                                    + log((double)dot));
            }
            BARS();
        }
    }
    #undef STEP
    #undef BARS

    // ---- fused final reduction + state reset (last CTA) ----
    __syncthreads();
    if (tid == 0) {
        __threadfence();
        unsigned int old = atomicAdd(&g_done, 1u);
        sflag = (old == NFCTA - 1) ? 1 : 0;
    }
    __syncthreads();
    if (sflag) {
        __threadfence();
        if (tid < 128) {
            shd[tid]       = (double)g_logZ[tid]       - (double)g_score[tid];
            shd[tid + 128] = (double)g_logZ[tid + 128] - (double)g_score[tid + 128];
            g_pairdone[tid]       = 0;
            g_pairdone[tid + 128] = 0;
        }
        if (tid < 2) g_ctr[tid] = 0;
        __syncthreads();
        for (int o = 128; o; o >>= 1) {
            if (tid < o) shd[tid] += shd[tid + o];
            __syncthreads();
        }
        if (tid == 0) {
            out[0] = (float)(shd[0] / (double)B_DIM);
            g_done = 0;
        }
    }
}

extern "C" void kernel_launch(void* const* d_in, const int* in_sizes, int n_in,
                              void* d_out, int out_size) {
    const float* emit   = (const float*)d_in[0];
    const int*   target = (const int*)d_in[1];
    const int*   mask   = (const int*)d_in[2];
    const float* trans  = (const float*)d_in[3];
    const float* strans = (const float*)d_in[4];
    const float* etrans = (const float*)d_in[5];

    scoreA1<<<NCHUNK, B_DIM>>>(emit, target, mask, trans);
    scoreA2<<<1, B_DIM>>>(target, strans, etrans);
    forward_kernel<<<NFCTA, 384>>>(emit, trans, strans, etrans, (float*)d_out);
}

// round 13
// speedup vs baseline: 1.6272x; 1.5001x over previous
#include <cuda_runtime.h>

#define T_DIM 512
#define B_DIM 256
#define N_DIM 128
#define BN    (B_DIM * N_DIM)
#define NCHUNK 128
#define TCHUNK (T_DIM / NCHUNK)
#define NFCTA  148
#define SLOTS  2
#define PSTR   68                    /* 64 floats + 16B pad per K-half */

#define LOGC_F 5.545177444479562f    /* ln 256 */
#define LOGC_D 5.545177444479562

__device__ float g_score[B_DIM];
__device__ float g_logZ[B_DIM];
__device__ int   g_len[B_DIM];
__device__ float g_part_s[NCHUNK * B_DIM];
__device__ int   g_part_c[NCHUNK * B_DIM];
__device__ int   g_units[B_DIM];          /* b sorted by len desc */
__device__ float g_vec[2][B_DIM][N_DIM];  /* meeting vectors */
__device__ float g_acc[2][B_DIM];         /* accumulated log scales */
__device__ int   g_ctr[2];                /* unit pop counters (self-reset) */
__device__ int   g_pairdone[B_DIM];       /* per-b arrival (self-reset) */
__device__ unsigned int g_done;           /* forward CTA completion (self-reset) */
__device__ unsigned int g_a1done;         /* score CTA completion (self-reset) */

// ---------------- f32x2 helpers ----------------
__device__ __forceinline__ unsigned long long pack2(float lo, float hi) {
    unsigned long long u;
    asm("mov.b64 %0, {%1,%2};" : "=l"(u) : "f"(lo), "f"(hi));
    return u;
}
__device__ __forceinline__ void unpack2(unsigned long long u, float& lo, float& hi) {
    asm("mov.b64 {%0,%1}, %2;" : "=f"(lo), "=f"(hi) : "l"(u));
}
__device__ __forceinline__ void ffma2(unsigned long long& d,
                                      unsigned long long a, unsigned long long b) {
    asm("fma.rn.f32x2 %0, %1, %2, %0;" : "+l"(d) : "l"(a), "l"(b));
}

// ---------------------------------------------------------------------------
// Fused score + schedule kernel (A1 + A2 via last-CTA pattern).
// Per-CTA phase: coalesced partial gold-path score + count for one t-chunk.
// Last CTA: combine partials + start/end bonuses, bitonic sort by length
// DESC, emit unit list. Self-resets g_a1done for graph replay.
// ---------------------------------------------------------------------------
__global__ void score_sched(const float* __restrict__ emit,
                            const int*   __restrict__ target,
                            const int*   __restrict__ mask,
                            const float* __restrict__ trans,
                            const float* __restrict__ strans,
                            const float* __restrict__ etrans) {
    __shared__ int key[B_DIM];
    __shared__ int lastc;

    const int b = threadIdx.x;
    const int c = blockIdx.x;
    const int t0 = c * TCHUNK;
    {
        float s = 0.f; int cnt = 0;
        #pragma unroll
        for (int t = t0; t < t0 + TCHUNK; ++t) {
            if (mask[t * B_DIM + b] != 0) {
                int tg = target[t * B_DIM + b];
                float v = emit[(size_t)t * BN + b * N_DIM + tg];
                if (t > 0) {
                    int tp = target[(t - 1) * B_DIM + b];
                    v += trans[tp * N_DIM + tg];
                }
                s += v; cnt += 1;
            }
        }
        g_part_s[c * B_DIM + b] = s;
        g_part_c[c * B_DIM + b] = cnt;
    }
    __threadfence();
    __syncthreads();
    if (b == 0) {
        unsigned int old = atomicAdd(&g_a1done, 1u);
        lastc = (old == NCHUNK - 1) ? 1 : 0;
    }
    __syncthreads();
    if (!lastc) return;
    __threadfence();

    // ---- combine partials + bonuses ----
    float s = 0.f; int cnt = 0;
    for (int cc = 0; cc < NCHUNK; ++cc) {
        s   += g_part_s[cc * B_DIM + b];
        cnt += g_part_c[cc * B_DIM + b];
    }
    s += strans[target[b]];
    s += etrans[target[(cnt - 1) * B_DIM + b]];
    g_score[b] = s;
    g_len[b]   = cnt;
    key[b] = (cnt << 9) | b;
    __syncthreads();

    // ---- bitonic sort DESC by length ----
    for (int k = 2; k <= B_DIM; k <<= 1) {
        for (int jj = k >> 1; jj > 0; jj >>= 1) {
            int p = b ^ jj;
            if (p > b) {
                int a0 = key[b], a1 = key[p];
                bool desc = ((b & k) != 0);
                if ((a0 > a1) == desc) { key[b] = a1; key[p] = a0; }
            }
            __syncthreads();
        }
    }
    g_units[b] = key[b] & 511;
    if (b == 0) g_a1done = 0;        // self-reset for graph replay
}

// ---------------------------------------------------------------------------
// Forward kernel (R10-identical): 148 CTAs x 256 threads = 2 chain slots x
// 128 threads. Slot thread (jp, h): h = stid&1 K-half, jp = stid>>1 ->
// owns j0=2jp, j1. Per step: 16 LDS.128 + 64 FFMA2 + 2 shfl + 1 bar.
// E (2 columns x K-half) in 128 regs, no spill, 2 warps/SMSP.
// Work-stealing over 512 half-units sorted desc (LPT); orientation fixed
// per slot (fwd/bwd). Renorm every 32 steps. Second finisher computes the
// meeting dot; last CTA does the fused (logZ-score)/B reduction + reset.
// ---------------------------------------------------------------------------
__global__ void __launch_bounds__(256, 1)
forward_kernel(const float* __restrict__ emit,
               const float* __restrict__ trans,
               const float* __restrict__ strans,
               const float* __restrict__ etrans,
               float* __restrict__ out) {
    __shared__ __align__(16) float pbuf[SLOTS][2][2 * PSTR];
    __shared__ float  wsum[SLOTS][4];
    __shared__ int    s_idx[SLOTS];
    __shared__ int    s_old[SLOTS];
    __shared__ int    sflag;
    __shared__ double shd[B_DIM];

    const int tid    = threadIdx.x;
    const int lane   = tid & 31;
    const int slot   = tid >> 7;              // 0..1
    const int stid   = tid & 127;
    const int h      = stid & 1;              // K-half
    const int jp     = stid >> 1;             // 0..63
    const int j0     = 2 * jp, j1 = j0 + 1;
    const int swarp  = stid >> 5;             // 0..3 within slot
    const int sg     = blockIdx.x * SLOTS + slot;
    const int orient = sg & 1;                // 0 = fwd, 1 = bwd
    const int widx   = j0 + ((j0 >> 6) << 2); // padded store index for p[j0]

    #define BARS() asm volatile("bar.sync %0, 128;" :: "r"(slot + 1) : "memory")

    // E half-columns (fwd) / half-rows (bwd) for j0 and j1, i-pair packed.
    unsigned long long E2A[32], E2B[32];
    if (orient == 0) {
        #pragma unroll
        for (int m = 0; m < 32; ++m) {
            int i = 64 * h + 2 * m;
            E2A[m] = pack2(__expf(trans[i * N_DIM + j0]),
                           __expf(trans[(i + 1) * N_DIM + j0]));
            E2B[m] = pack2(__expf(trans[i * N_DIM + j1]),
                           __expf(trans[(i + 1) * N_DIM + j1]));
        }
    } else {
        #pragma unroll
        for (int m = 0; m < 32; ++m) {
            int i = 64 * h + 2 * m;
            E2A[m] = pack2(__expf(trans[j0 * N_DIM + i]),
                           __expf(trans[j0 * N_DIM + i + 1]));
            E2B[m] = pack2(__expf(trans[j1 * N_DIM + i]),
                           __expf(trans[j1 * N_DIM + i + 1]));
        }
    }
    const float sj0  = strans[j0], sj1 = strans[j1];
    const float etj0 = etrans[j0], etj1 = etrans[j1];

    float* pb0 = pbuf[slot][0];
    float* pb1 = pbuf[slot][1];
    const int roff = 17 * h;                  // ulonglong2 offset of my K-half

    float v0, v1;

    #define STEP(ECRAW, PR, PW, TT) do {                                     \
        float ee = ((TT) == lastSpec) ? 0.f : ((ECRAW).x - LOGC_F);          \
        float ef = ((TT) == lastSpec) ? 0.f : ((ECRAW).y - LOGC_F);          \
        float ee0 = __expf(ee), ee1 = __expf(ef);                            \
        const ulonglong2* pu = (const ulonglong2*)(PR) + roff;               \
        unsigned long long a0 = 0ull, a1 = 0ull, b0 = 0ull, b1 = 0ull;       \
        _Pragma("unroll")                                                    \
        for (int k = 0; k < 16; ++k) {                                       \
            ulonglong2 x = pu[k];                                            \
            ffma2(a0, x.x, E2A[2 * k]);                                      \
            ffma2(a1, x.y, E2A[2 * k + 1]);                                  \
            ffma2(b0, x.x, E2B[2 * k]);                                      \
            ffma2(b1, x.y, E2B[2 * k + 1]);                                  \
        }                                                                    \
        float f0, f1, f2, f3, g0, g1, g2, g3;                                \
        unpack2(a0, f0, f1); unpack2(a1, f2, f3);                            \
        unpack2(b0, g0, g1); unpack2(b1, g2, g3);                            \
        float s0 = (f0 + f1) + (f2 + f3);                                    \
        float s1 = (g0 + g1) + (g2 + g3);                                    \
        s0 += __shfl_xor_sync(0xffffffffu, s0, 1);                           \
        s1 += __shfl_xor_sync(0xffffffffu, s1, 1);                           \
        v0 = s0 * ee0; v1 = s1 * ee1;                                        \
        if (((TT) & 31) == 0) {                                              \
            float r = h ? 0.f : (v0 + v1);                                   \
            _Pragma("unroll")                                                \
            for (int o = 16; o; o >>= 1)                                     \
                r += __shfl_xor_sync(0xffffffffu, r, o);                     \
            if (lane == 0) wsum[slot][swarp] = r;                            \
            BARS();                                                          \
            float ss = (wsum[slot][0] + wsum[slot][1])                       \
                     + (wsum[slot][2] + wsum[slot][3]);                      \
            float inv = 1.f / ss;                                            \
            v0 *= inv; v1 *= inv;                                            \
            acc_log += __logf(ss);                                           \
        }                                                                    \
        if (h == 0) *(float2*)&(PW)[widx] = make_float2(v0, v1);             \
        BARS();                                                              \
    } while (0)

    // ---- work-stealing unit loop ----
    for (;;) {
        if (stid == 0) s_idx[slot] = atomicAdd(&g_ctr[orient], 1);
        BARS();
        const int idx = s_idx[slot];
        if (idx >= B_DIM) break;

        const int b   = g_units[idx];
        const int len = g_len[b];
        const int m   = (len - 1) >> 1;
        const int nsteps   = orient ? (len - 1 - m) : m;
        const int lastSpec = orient ? nsteps : -1;
        const int e0i      = orient ? (len - 1) : 0;
        const int estep    = orient ? -1 : 1;
        const float* eb    = emit + b * N_DIM + j0;

        float acc_log = 0.f;
        if (orient == 0) {
            float2 e0v = *(const float2*)eb;
            v0 = __expf(sj0 + e0v.x);
            v1 = __expf(sj1 + e0v.y);
        } else if (nsteps == 0) {
            v0 = __expf(etj0);
            v1 = __expf(etj1);
        } else {
            float2 e0v = *(const float2*)(eb + (size_t)(len - 1) * BN);
            v0 = __expf(e0v.x + etj0 - LOGC_F);
            v1 = __expf(e0v.y + etj1 - LOGC_F);
        }

        if (nsteps > 0) {
            if (h == 0) *(float2*)&pb0[widx] = make_float2(v0, v1);
            #define LDE(TT) (*(const float2*)(eb + (size_t)max(0, min(len - 1, e0i + estep * (TT))) * BN))
            float2 e0 = LDE(1), e1 = LDE(2), e2 = LDE(3), e3 = LDE(4);
            BARS();
            int t = 1;
            #pragma unroll 1
            for (; t + 3 <= nsteps; t += 4) {
                float2 n0 = LDE(t + 4), n1 = LDE(t + 5),
                       n2 = LDE(t + 6), n3 = LDE(t + 7);
                STEP(e0, pb0, pb1, t);
                STEP(e1, pb1, pb0, t + 1);
                STEP(e2, pb0, pb1, t + 2);
                STEP(e3, pb1, pb0, t + 3);
                e0 = n0; e1 = n1; e2 = n2; e3 = n3;
            }
            if (t <= nsteps) { STEP(e0, pb0, pb1, t); ++t; }
            if (t <= nsteps) { STEP(e1, pb1, pb0, t); ++t; }
            if (t <= nsteps) { STEP(e2, pb0, pb1, t); }
            #undef LDE
        }

        // publish this half; second finisher computes the meeting dot.
        if (h == 0) {
            g_vec[orient][b][j0] = v0;
            g_vec[orient][b][j1] = v1;
            if (stid == 0) g_acc[orient][b] = acc_log;
        }
        __threadfence();
        BARS();
        if (stid == 0) s_old[slot] = atomicAdd(&g_pairdone[b], 1);
        BARS();
        if (s_old[slot] == 1) {
            __threadfence();
            float r = h ? 0.f : (v0 * g_vec[orient ^ 1][b][j0]
                               + v1 * g_vec[orient ^ 1][b][j1]);
            #pragma unroll
            for (int o = 16; o; o >>= 1)
                r += __shfl_xor_sync(0xffffffffu, r, o);
            if (lane == 0) wsum[slot][swarp] = r;
            BARS();
            if (stid == 0) {
                float dot = (wsum[slot][0] + wsum[slot][1])
                          + (wsum[slot][2] + wsum[slot][3]);
                g_logZ[b] = (float)((double)acc_log
                                    + (double)g_acc[orient ^ 1][b]
                                    + (double)(len - 1) * LOGC_D
                                    + log((double)dot));
            }
            BARS();
        }
    }
    #undef STEP
    #undef BARS

    // ---- fused final reduction + state reset (last CTA) ----
    __syncthreads();
    if (tid == 0) {
        __threadfence();
        unsigned int old = atomicAdd(&g_done, 1u);
        sflag = (old == NFCTA - 1) ? 1 : 0;
    }
    __syncthreads();
    if (sflag) {
        __threadfence();
        if (tid < 128) {
            shd[tid]       = (double)g_logZ[tid]       - (double)g_score[tid];
            shd[tid + 128] = (double)g_logZ[tid + 128] - (double)g_score[tid + 128];
            g_pairdone[tid]       = 0;
            g_pairdone[tid + 128] = 0;
        }
        if (tid < 2) g_ctr[tid] = 0;
        __syncthreads();
        for (int o = 128; o; o >>= 1) {
            if (tid < o) shd[tid] += shd[tid + o];
            __syncthreads();
        }
        if (tid == 0) {
            out[0] = (float)(shd[0] / (double)B_DIM);
            g_done = 0;
        }
    }
}

extern "C" void kernel_launch(void* const* d_in, const int* in_sizes, int n_in,
                              void* d_out, int out_size) {
    const float* emit   = (const float*)d_in[0];
    const int*   target = (const int*)d_in[1];
    const int*   mask   = (const int*)d_in[2];
    const float* trans  = (const float*)d_in[3];
    const float* strans = (const float*)d_in[4];
    const float* etrans = (const float*)d_in[5];

    score_sched<<<NCHUNK, B_DIM>>>(emit, target, mask, trans, strans, etrans);
    forward_kernel<<<NFCTA, 256>>>(emit, trans, strans, etrans, (float*)d_out);
}